// round 7
// baseline (speedup 1.0000x reference)
#include <cuda_runtime.h>
#include <cstdint>

#define B_  4
#define Qn  1024
#define Kn  1024
#define QS  256
#define KSZ 256
#define Hn  32
#define VD  256
#define TQ  8
#define TK  128

// Device-global scratch (no runtime allocation allowed)
__device__ float g_fq[B_ * Qn * Hn];
__device__ float g_fk[B_ * Kn * Hn];

// ---------------- helpers ----------------

__device__ __forceinline__ float fast_tanh(float x) {
    float y;
    asm("tanh.approx.f32 %0, %1;" : "=f"(y) : "f"(x));
    return y;
}

__device__ __forceinline__ float warp_sum(float v) {
    #pragma unroll
    for (int o = 16; o > 0; o >>= 1) v += __shfl_xor_sync(0xFFFFFFFFu, v, o);
    return v;
}

__device__ __forceinline__ unsigned long long pack2(float lo, float hi) {
    unsigned long long r;
    asm("mov.b64 %0, {%1, %2};" : "=l"(r) : "f"(lo), "f"(hi));
    return r;
}
__device__ __forceinline__ void unpack2(unsigned long long a, float& lo, float& hi) {
    asm("mov.b64 {%0, %1}, %2;" : "=f"(lo), "=f"(hi) : "l"(a));
}
__device__ __forceinline__ void fma2(unsigned long long& a, unsigned long long v, unsigned long long p) {
    asm("fma.rn.f32x2 %0, %1, %2, %0;" : "+l"(a) : "l"(v), "l"(p));
}

__device__ __forceinline__ void cp_async16(unsigned int dst_smem, const void* src) {
    asm volatile("cp.async.ca.shared.global [%0], [%1], 16;" :: "r"(dst_smem), "l"(src));
}
__device__ __forceinline__ void cp_async_commit() {
    asm volatile("cp.async.commit_group;");
}
__device__ __forceinline__ void cp_async_wait0() {
    asm volatile("cp.async.wait_group 0;");
}

// ---------------- kernel 1: projections fq = q@Wq+bq, fk = k@Wk+bk ----------------

__global__ __launch_bounds__(256)
void proj_kernel(const float* __restrict__ queries, const float* __restrict__ keys,
                 const float* __restrict__ Wq, const float* __restrict__ bq,
                 const float* __restrict__ Wk, const float* __restrict__ bk,
                 const int* __restrict__ valid_lens) {
    __shared__ float xs[8][QS];
    int w = threadIdx.x >> 5, lane = threadIdx.x & 31;
    int row = blockIdx.x * 8 + w;

    const float* src; const float* W; const float* bias; float* dst;
    if (row < B_ * Qn) {
        src = queries + (size_t)row * QS; W = Wq; bias = bq; dst = g_fq + (size_t)row * Hn;
    } else {
        int r2 = row - B_ * Qn;
        // fk rows at/after valid_len are masked to p=0 in attn, skip them.
        if ((r2 & (Kn - 1)) >= valid_lens[r2 >> 10]) return;
        src = keys + (size_t)r2 * KSZ; W = Wk; bias = bk; dst = g_fk + (size_t)r2 * Hn;
    }

    {
        const float4* s4 = (const float4*)src;
        float4* x4 = (float4*)xs[w];
        x4[lane]      = s4[lane];
        x4[lane + 32] = s4[lane + 32];
    }
    __syncwarp();

    float sum = 0.0f;
    #pragma unroll 8
    for (int j = 0; j < QS; j++) sum = fmaf(xs[w][j], W[j * Hn + lane], sum);
    dst[lane] = sum + bias[lane];
}

// ---------------- kernel 2: fused additive attention ----------------
// grid = (B, Q/TQ) = 512 CTAs, block = 256 (8 warps), 4 CTAs/SM (64-reg target)
// -> 592 CTA slots >= 512: single full wave, no straggler tail.
// Phase A: warp w = q-row w, lanes = k (4/lane). No online softmax (scores
// bounded by ||w_v||_1 since |tanh|<=1 -> exp can't overflow in fp32).
// Phase B: warp w = (k-slice (w>>1)*32, v-half (w&1)*128); acc = 8q x 2 u64 = 32 regs.
// fk_s double-buffered via cp.async; pT2 SINGLE-buffered (saves 10KB so 4 CTAs
// fit in 227KB smem) at the cost of a second barrier per chunk.

__global__ __launch_bounds__(256, 4)
void attn_kernel(const float* __restrict__ values, const int* __restrict__ valid_lens,
                 const float* __restrict__ wvec, float* __restrict__ out) {
    __shared__ float fk_s[2][TK * 36];                        // [k][h], stride 36 floats
    __shared__ __align__(16) unsigned long long pT2[TK * 10]; // [k][q] dup pair {p,p}, stride 10 u64
    __shared__ float fq_s[TQ * 32];
    __shared__ float wv_s[32];
    __shared__ float l_s[TQ];

    const int tid  = threadIdx.x;
    const int w    = tid >> 5;
    const int lane = tid & 31;
    const int b    = blockIdx.x;
    const int q0   = blockIdx.y * TQ;
    const int valid = valid_lens[b];

    fq_s[w * 32 + lane] = g_fq[((size_t)(b * Qn + q0 + w)) * Hn + lane];
    if (tid < 32) wv_s[tid] = wvec[tid];

    float l_run = 0.0f;                   // per-lane partial row-sum for q=w
    unsigned long long acc[TQ][2];        // 8q x (4 floats of this warp's v-half)
    #pragma unroll
    for (int q = 0; q < TQ; q++) { acc[q][0] = 0ull; acc[q][1] = 0ull; }

    const float* vbatch = values + (size_t)b * Kn * VD;
    const int nchunks = (valid + TK - 1) / TK;

    // Preload chunk 0 into buffer 0 via cp.async
    {
        const float4* src = (const float4*)(g_fk + ((size_t)(b * Kn)) * Hn);
        #pragma unroll
        for (int r = 0; r < 4; r++) {
            int idx = tid + 256 * r;
            unsigned int dst = (unsigned int)__cvta_generic_to_shared(
                &((float4*)fk_s[0])[(idx >> 3) * 9 + (idx & 7)]);
            cp_async16(dst, &src[idx]);
        }
        cp_async_commit();
        cp_async_wait0();
    }
    __syncthreads();

    int buf = 0;
    for (int c = 0; c < nchunks; c++) {
        const int kb = c * TK;
        const bool full = (kb + TK <= valid);
        const bool has_next = (c + 1 < nchunks);

        // ---- Prefetch next fk chunk straight into the spare smem buffer ----
        if (has_next) {
            const float4* src = (const float4*)(g_fk + ((size_t)(b * Kn + kb + TK)) * Hn);
            #pragma unroll
            for (int r = 0; r < 4; r++) {
                int idx = tid + 256 * r;
                unsigned int dst = (unsigned int)__cvta_generic_to_shared(
                    &((float4*)fk_s[buf ^ 1])[(idx >> 3) * 9 + (idx & 7)]);
                cp_async16(dst, &src[idx]);
            }
            cp_async_commit();
        }

        // -------- Phase A: scores for q=w, k=lane+32i --------
        float sacc[4] = {0.f, 0.f, 0.f, 0.f};
        {
            const float4* fq4 = (const float4*)(fq_s + w * 32);
            const float4* wv4 = (const float4*)wv_s;
            const float4* fk4 = (const float4*)fk_s[buf];
            #pragma unroll
            for (int hb = 0; hb < 8; hb++) {
                float4 a = fq4[hb];
                float4 g = wv4[hb];
                #pragma unroll
                for (int i = 0; i < 4; i++) {
                    float4 f = fk4[(lane + 32 * i) * 9 + hb];
                    sacc[i] = fmaf(g.x, fast_tanh(a.x + f.x), sacc[i]);
                    sacc[i] = fmaf(g.y, fast_tanh(a.y + f.y), sacc[i]);
                    sacc[i] = fmaf(g.z, fast_tanh(a.z + f.z), sacc[i]);
                    sacc[i] = fmaf(g.w, fast_tanh(a.w + f.w), sacc[i]);
                }
            }
        }

        // -------- p = exp(score) (bounded, no max shift), mask, store dup-pair --------
        if (full) {
            #pragma unroll
            for (int i = 0; i < 4; i++) {
                float p = __expf(sacc[i]);
                l_run += p;
                pT2[(lane + 32 * i) * 10 + w] = pack2(p, p);
            }
        } else {
            #pragma unroll
            for (int i = 0; i < 4; i++) {
                float p = (kb + lane + 32 * i < valid) ? __expf(sacc[i]) : 0.0f;
                l_run += p;
                pT2[(lane + 32 * i) * 10 + w] = pack2(p, p);
            }
        }

        if (has_next) cp_async_wait0();
        __syncthreads();   // pT2 visible to all warps; fk_s[buf^1] filled for next A

        // -------- Phase B: P@V. warp w = (k-slice (w>>1)*32, v-half (w&1)*128) --------
        {
            const int kloc0 = (w >> 1) * 32;
            const int voff  = (w & 1) * 128;
            const unsigned long long* pbase = pT2 + kloc0 * 10;
            const float* vb = vbatch + (size_t)(kb + kloc0) * VD + voff;

            int kend;
            if (full) kend = 32;
            else { int rem = valid - kb - kloc0; kend = rem < 32 ? (rem < 0 ? 0 : rem) : 32; }

            #pragma unroll 8
            for (int kk = 0; kk < kend; kk++) {
                ulonglong2 v = __ldg((const ulonglong2*)(vb + (size_t)kk * VD) + lane);
                const ulonglong2* prow2 = (const ulonglong2*)(pbase + kk * 10);
                #pragma unroll
                for (int qp = 0; qp < 4; qp++) {
                    ulonglong2 pp = prow2[qp];       // broadcast LDS.128
                    fma2(acc[2 * qp][0],     v.x, pp.x);
                    fma2(acc[2 * qp][1],     v.y, pp.x);
                    fma2(acc[2 * qp + 1][0], v.x, pp.y);
                    fma2(acc[2 * qp + 1][1], v.y, pp.y);
                }
            }
        }

        // pT2 is single-buffered: next chunk's phase A overwrites it, so all
        // warps must be done reading before any warp proceeds.
        if (has_next) __syncthreads();
        buf ^= 1;
    }

    // -------- Epilogue: row-sums, then single-barrier cross-warp reduction --------
    float l = warp_sum(l_run);
    if (lane == 0) l_s[w] = l;

    // bufp layout: [q][w][128] floats = 32KB, lives in fk_s (36KB). Safe: phase B
    // reads only pT2/values, and all phase-A consumers of fk_s are done.
    float* bufp = fk_s[0];
    #pragma unroll
    for (int q = 0; q < TQ; q++) {
        float f0, f1, f2, f3;
        unpack2(acc[q][0], f0, f1);
        unpack2(acc[q][1], f2, f3);
        float* d = bufp + (q * 8 + w) * 128 + lane * 4;
        d[0] = f0; d[1] = f1; d[2] = f2; d[3] = f3;
    }
    __syncthreads();

    // out element (q, v=tid): sum the 4 warps holding v-half (tid>>7)
    {
        const int vhalf = tid >> 7;
        const int idx   = tid & 127;
        const size_t obase = ((size_t)(b * Qn + q0)) * VD + tid;
        #pragma unroll
        for (int q = 0; q < TQ; q++) {
            const float* s = bufp + q * 1024 + vhalf * 128 + idx;
            float tot = s[0] + s[256] + s[512] + s[768];
            out[obase + (size_t)q * VD] = tot * (1.0f / l_s[q]);
        }
    }
}

// ---------------- launch ----------------

extern "C" void kernel_launch(void* const* d_in, const int* in_sizes, int n_in,
                              void* d_out, int out_size) {
    const float* keys       = (const float*)d_in[0];
    const float* queries    = (const float*)d_in[1];
    const float* values     = (const float*)d_in[2];
    const int*   valid_lens = (const int*)d_in[3];
    const float* W_q        = (const float*)d_in[4];
    const float* b_q        = (const float*)d_in[5];
    const float* W_k        = (const float*)d_in[6];
    const float* b_k        = (const float*)d_in[7];
    const float* w_v        = (const float*)d_in[8];
    // b_v (d_in[9]) is softmax-invariant and intentionally unused.
    float* out = (float*)d_out;

    int total_rows = B_ * (Qn + Kn);            // 8192
    proj_kernel<<<total_rows / 8, 256>>>(queries, keys, W_q, b_q, W_k, b_k, valid_lens);

    dim3 grid(B_, Qn / TQ);
    attn_kernel<<<grid, 256>>>(values, valid_lens, w_v, out);
}

// round 8
// speedup vs baseline: 1.1837x; 1.1837x over previous
#include <cuda_runtime.h>
#include <cstdint>

#define B_  4
#define Qn  1024
#define Kn  1024
#define QS  256
#define KSZ 256
#define Hn  32
#define VD  256
#define TQ  8
#define TK  128

// Device-global scratch (no runtime allocation allowed)
__device__ float g_fq[B_ * Qn * Hn];
__device__ float g_fk[B_ * Kn * Hn];

typedef unsigned long long u64;

// ---------------- helpers ----------------

__device__ __forceinline__ float fast_tanh(float x) {
    float y;
    asm("tanh.approx.f32 %0, %1;" : "=f"(y) : "f"(x));
    return y;
}

__device__ __forceinline__ float warp_sum(float v) {
    #pragma unroll
    for (int o = 16; o > 0; o >>= 1) v += __shfl_xor_sync(0xFFFFFFFFu, v, o);
    return v;
}

__device__ __forceinline__ u64 pack2(float lo, float hi) {
    u64 r;
    asm("mov.b64 %0, {%1, %2};" : "=l"(r) : "f"(lo), "f"(hi));
    return r;
}
__device__ __forceinline__ void unpack2(u64 a, float& lo, float& hi) {
    asm("mov.b64 {%0, %1}, %2;" : "=f"(lo), "=f"(hi) : "l"(a));
}
__device__ __forceinline__ u64 add2(u64 a, u64 b) {
    u64 r;
    asm("add.rn.f32x2 %0, %1, %2;" : "=l"(r) : "l"(a), "l"(b));
    return r;
}
__device__ __forceinline__ void fma2(u64& a, u64 v, u64 p) {
    asm("fma.rn.f32x2 %0, %1, %2, %0;" : "+l"(a) : "l"(v), "l"(p));
}

__device__ __forceinline__ void cp_async16(unsigned int dst_smem, const void* src) {
    asm volatile("cp.async.ca.shared.global [%0], [%1], 16;" :: "r"(dst_smem), "l"(src));
}
__device__ __forceinline__ void cp_async_commit() {
    asm volatile("cp.async.commit_group;");
}
__device__ __forceinline__ void cp_async_wait0() {
    asm volatile("cp.async.wait_group 0;");
}

// ---------------- kernel 1: projections fq = q@Wq+bq, fk = k@Wk+bk ----------------
// 4 independent FMA chains (breaks the 256-deep serial dependence) + float4 x.

__global__ __launch_bounds__(256)
void proj_kernel(const float* __restrict__ queries, const float* __restrict__ keys,
                 const float* __restrict__ Wq, const float* __restrict__ bq,
                 const float* __restrict__ Wk, const float* __restrict__ bk,
                 const int* __restrict__ valid_lens) {
    __shared__ float xs[8][QS];
    int w = threadIdx.x >> 5, lane = threadIdx.x & 31;
    int row = blockIdx.x * 8 + w;

    const float* src; const float* W; const float* bias; float* dst;
    if (row < B_ * Qn) {
        src = queries + (size_t)row * QS; W = Wq; bias = bq; dst = g_fq + (size_t)row * Hn;
    } else {
        int r2 = row - B_ * Qn;
        // fk rows at/after valid_len are masked to p=0 in attn, skip them.
        if ((r2 & (Kn - 1)) >= valid_lens[r2 >> 10]) return;
        src = keys + (size_t)r2 * KSZ; W = Wk; bias = bk; dst = g_fk + (size_t)r2 * Hn;
    }

    {
        const float4* s4 = (const float4*)src;
        float4* x4 = (float4*)xs[w];
        x4[lane]      = s4[lane];
        x4[lane + 32] = s4[lane + 32];
    }
    __syncwarp();

    float s0 = 0.f, s1 = 0.f, s2 = 0.f, s3 = 0.f;
    const float4* x4 = (const float4*)xs[w];
    #pragma unroll 16
    for (int j4 = 0; j4 < QS / 4; j4++) {
        float4 x = x4[j4];
        const float* Wp = W + (4 * j4) * Hn + lane;
        s0 = fmaf(x.x, Wp[0],      s0);
        s1 = fmaf(x.y, Wp[Hn],     s1);
        s2 = fmaf(x.z, Wp[2 * Hn], s2);
        s3 = fmaf(x.w, Wp[3 * Hn], s3);
    }
    dst[lane] = (s0 + s1) + (s2 + s3) + bias[lane];
}

// ---------------- kernel 2: fused additive attention ----------------
// grid = (B, Q/TQ), block = 256 (8 warps), 3 CTAs/SM (R5b config — best known).
// Phase A: warp w = q-row w, lanes = k (4/lane); packed f32x2 add/fma around
// scalar MUFU tanh. No online softmax (scores bounded by ||w_v||_1, |tanh|<=1).
// Phase B: warp w = (k-slice (w>>1)*32, v-half (w&1)*128); acc = 8q x 2 u64.
// fk_s AND pT2 double-buffered; ONE barrier per chunk; cp.async fk prefetch.

__global__ __launch_bounds__(256, 3)
void attn_kernel(const float* __restrict__ values, const int* __restrict__ valid_lens,
                 const float* __restrict__ wvec, float* __restrict__ out) {
    __shared__ float fk_s[2][TK * 36];                   // [k][h], stride 36 floats
    __shared__ __align__(16) u64 pT2[2][TK * 10];        // [k][q] dup pair {p,p}, stride 10 u64
    __shared__ float fq_s[TQ * 32];
    __shared__ float wv_s[32];
    __shared__ float l_s[TQ];

    const int tid  = threadIdx.x;
    const int w    = tid >> 5;
    const int lane = tid & 31;
    const int b    = blockIdx.x;
    const int q0   = blockIdx.y * TQ;
    const int valid = valid_lens[b];

    fq_s[w * 32 + lane] = g_fq[((size_t)(b * Qn + q0 + w)) * Hn + lane];
    if (tid < 32) wv_s[tid] = wvec[tid];

    float l_run = 0.0f;                   // per-lane partial row-sum for q=w
    u64 acc[TQ][2];                       // 8q x (4 floats of this warp's v-half)
    #pragma unroll
    for (int q = 0; q < TQ; q++) { acc[q][0] = 0ull; acc[q][1] = 0ull; }

    const float* vbatch = values + (size_t)b * Kn * VD;
    const int nchunks = (valid + TK - 1) / TK;

    // Preload chunk 0 into buffer 0 via cp.async
    {
        const float4* src = (const float4*)(g_fk + ((size_t)(b * Kn)) * Hn);
        #pragma unroll
        for (int r = 0; r < 4; r++) {
            int idx = tid + 256 * r;
            unsigned int dst = (unsigned int)__cvta_generic_to_shared(
                &((float4*)fk_s[0])[(idx >> 3) * 9 + (idx & 7)]);
            cp_async16(dst, &src[idx]);
        }
        cp_async_commit();
        cp_async_wait0();
    }
    __syncthreads();

    int buf = 0;
    for (int c = 0; c < nchunks; c++) {
        const int kb = c * TK;
        const bool full = (kb + TK <= valid);
        const bool has_next = (c + 1 < nchunks);

        // ---- Prefetch next fk chunk straight into the spare smem buffer ----
        if (has_next) {
            const float4* src = (const float4*)(g_fk + ((size_t)(b * Kn + kb + TK)) * Hn);
            #pragma unroll
            for (int r = 0; r < 4; r++) {
                int idx = tid + 256 * r;
                unsigned int dst = (unsigned int)__cvta_generic_to_shared(
                    &((float4*)fk_s[buf ^ 1])[(idx >> 3) * 9 + (idx & 7)]);
                cp_async16(dst, &src[idx]);
            }
            cp_async_commit();
        }

        // -------- Phase A: scores for q=w, k=lane+32i (packed f32x2) --------
        u64 spair[4] = {0ull, 0ull, 0ull, 0ull};   // per-i accumulator pair {even,odd}
        {
            const ulonglong2* fq2 = (const ulonglong2*)(fq_s + w * 32);
            const ulonglong2* wv2 = (const ulonglong2*)wv_s;
            const ulonglong2* fk2 = (const ulonglong2*)fk_s[buf];
            #pragma unroll
            for (int hb = 0; hb < 8; hb++) {
                ulonglong2 a = fq2[hb];
                ulonglong2 g = wv2[hb];
                #pragma unroll
                for (int i = 0; i < 4; i++) {
                    ulonglong2 f = fk2[(lane + 32 * i) * 9 + hb];
                    u64 s0 = add2(a.x, f.x);       // {fq0+fk0, fq1+fk1}
                    u64 s1 = add2(a.y, f.y);
                    float e0, e1, e2, e3;
                    unpack2(s0, e0, e1);
                    unpack2(s1, e2, e3);
                    u64 t0 = pack2(fast_tanh(e0), fast_tanh(e1));
                    u64 t1 = pack2(fast_tanh(e2), fast_tanh(e3));
                    fma2(spair[i], g.x, t0);
                    fma2(spair[i], g.y, t1);
                }
            }
        }

        // -------- p = exp(score) (bounded, no max shift), mask, store dup-pair --------
        #pragma unroll
        for (int i = 0; i < 4; i++) {
            float lo, hi;
            unpack2(spair[i], lo, hi);
            float score = lo + hi;
            float p;
            if (full) p = __expf(score);
            else      p = (kb + lane + 32 * i < valid) ? __expf(score) : 0.0f;
            l_run += p;
            pT2[buf][(lane + 32 * i) * 10 + w] = pack2(p, p);
        }

        if (has_next) cp_async_wait0();
        __syncthreads();   // pT2[buf] visible; fk_s[buf^1] filled for next A

        // -------- Phase B: P@V. warp w = (k-slice (w>>1)*32, v-half (w&1)*128) --------
        {
            const int kloc0 = (w >> 1) * 32;
            const int voff  = (w & 1) * 128;
            const u64* pbase = pT2[buf] + kloc0 * 10;
            const float* vb = vbatch + (size_t)(kb + kloc0) * VD + voff;

            int kend;
            if (full) kend = 32;
            else { int rem = valid - kb - kloc0; kend = rem < 32 ? (rem < 0 ? 0 : rem) : 32; }

            #pragma unroll 8
            for (int kk = 0; kk < kend; kk++) {
                ulonglong2 v = __ldg((const ulonglong2*)(vb + (size_t)kk * VD) + lane);
                const ulonglong2* prow2 = (const ulonglong2*)(pbase + kk * 10);
                #pragma unroll
                for (int qp = 0; qp < 4; qp++) {
                    ulonglong2 pp = prow2[qp];       // broadcast LDS.128
                    fma2(acc[2 * qp][0],     v.x, pp.x);
                    fma2(acc[2 * qp][1],     v.y, pp.x);
                    fma2(acc[2 * qp + 1][0], v.x, pp.y);
                    fma2(acc[2 * qp + 1][1], v.y, pp.y);
                }
            }
        }
        buf ^= 1;
    }

    // -------- Epilogue: row-sums, then single-barrier cross-warp reduction --------
    float l = warp_sum(l_run);
    if (lane == 0) l_s[w] = l;

    // bufp layout: [q][w][128] floats = 32KB, lives in fk_s (36KB+)
    float* bufp = fk_s[0];
    #pragma unroll
    for (int q = 0; q < TQ; q++) {
        float f0, f1, f2, f3;
        unpack2(acc[q][0], f0, f1);
        unpack2(acc[q][1], f2, f3);
        float* d = bufp + (q * 8 + w) * 128 + lane * 4;
        d[0] = f0; d[1] = f1; d[2] = f2; d[3] = f3;
    }
    __syncthreads();

    // out element (q, v=tid): sum the 4 warps holding v-half (tid>>7)
    {
        const int vhalf = tid >> 7;
        const int idx   = tid & 127;
        const size_t obase = ((size_t)(b * Qn + q0)) * VD + tid;
        #pragma unroll
        for (int q = 0; q < TQ; q++) {
            const float* s = bufp + q * 1024 + vhalf * 128 + idx;
            float tot = s[0] + s[256] + s[512] + s[768];
            out[obase + (size_t)q * VD] = tot * (1.0f / l_s[q]);
        }
    }
}

// ---------------- launch ----------------

extern "C" void kernel_launch(void* const* d_in, const int* in_sizes, int n_in,
                              void* d_out, int out_size) {
    const float* keys       = (const float*)d_in[0];
    const float* queries    = (const float*)d_in[1];
    const float* values     = (const float*)d_in[2];
    const int*   valid_lens = (const int*)d_in[3];
    const float* W_q        = (const float*)d_in[4];
    const float* b_q        = (const float*)d_in[5];
    const float* W_k        = (const float*)d_in[6];
    const float* b_k        = (const float*)d_in[7];
    const float* w_v        = (const float*)d_in[8];
    // b_v (d_in[9]) is softmax-invariant and intentionally unused.
    float* out = (float*)d_out;

    int total_rows = B_ * (Qn + Kn);            // 8192
    proj_kernel<<<total_rows / 8, 256>>>(queries, keys, W_q, b_q, W_k, b_k, valid_lens);

    dim3 grid(B_, Qn / TQ);
    attn_kernel<<<grid, 256>>>(values, valid_lens, w_v, out);
}

// round 9
// speedup vs baseline: 1.2320x; 1.0408x over previous
#include <cuda_runtime.h>
#include <cstdint>

#define B_  4
#define Qn  1024
#define Kn  1024
#define QS  256
#define KSZ 256
#define Hn  32
#define VD  256
#define TQ  8
#define TK  128

// Device-global scratch (no runtime allocation allowed)
__device__ float g_fq[B_ * Qn * Hn];
__device__ float g_fk[B_ * Kn * Hn];

typedef unsigned long long u64;

// ---------------- helpers ----------------

__device__ __forceinline__ float fast_tanh(float x) {
    float y;
    asm("tanh.approx.f32 %0, %1;" : "=f"(y) : "f"(x));
    return y;
}

__device__ __forceinline__ float warp_sum(float v) {
    #pragma unroll
    for (int o = 16; o > 0; o >>= 1) v += __shfl_xor_sync(0xFFFFFFFFu, v, o);
    return v;
}

__device__ __forceinline__ u64 pack2(float lo, float hi) {
    u64 r;
    asm("mov.b64 %0, {%1, %2};" : "=l"(r) : "f"(lo), "f"(hi));
    return r;
}
__device__ __forceinline__ void unpack2(u64 a, float& lo, float& hi) {
    asm("mov.b64 {%0, %1}, %2;" : "=f"(lo), "=f"(hi) : "l"(a));
}
__device__ __forceinline__ u64 add2(u64 a, u64 b) {
    u64 r;
    asm("add.rn.f32x2 %0, %1, %2;" : "=l"(r) : "l"(a), "l"(b));
    return r;
}
__device__ __forceinline__ void fma2(u64& a, u64 v, u64 p) {
    asm("fma.rn.f32x2 %0, %1, %2, %0;" : "+l"(a) : "l"(v), "l"(p));
}

__device__ __forceinline__ void cp_async16(unsigned int dst_smem, const void* src) {
    asm volatile("cp.async.ca.shared.global [%0], [%1], 16;" :: "r"(dst_smem), "l"(src));
}
__device__ __forceinline__ void cp_async_commit() {
    asm volatile("cp.async.commit_group;");
}
__device__ __forceinline__ void cp_async_wait0() {
    asm volatile("cp.async.wait_group 0;");
}

// ---------------- kernel 1: projections fq = q@Wq+bq, fk = k@Wk+bk ----------------
// warp = 2 rows; lane = (row-group = lane>>4, h-pair = lane&15).
// Per 4 j: 1 broadcast LDG.128 (x) + 4 LDG.64 (W h-pair, L1-resident 32KB) +
// 4 pack MOV + 4 fma2. Four independent accumulator chains. u64 output stores.

__global__ __launch_bounds__(256)
void proj_kernel(const float* __restrict__ queries, const float* __restrict__ keys,
                 const float* __restrict__ Wq, const float* __restrict__ bq,
                 const float* __restrict__ Wk, const float* __restrict__ bk,
                 const int* __restrict__ valid_lens) {
    const int wid  = threadIdx.x >> 5;
    const int lane = threadIdx.x & 31;
    const int hp   = lane & 15;          // h-pair index: h = 2hp, 2hp+1
    const int rg   = lane >> 4;          // row within the warp's pair
    const int row  = (blockIdx.x * 8 + wid) * 2 + rg;

    const float* src; const u64* Wp; const u64* biasp; u64* dst;
    if (row < B_ * Qn) {
        src = queries + (size_t)row * QS;
        Wp = (const u64*)Wq; biasp = (const u64*)bq;
        dst = (u64*)g_fq + (size_t)row * (Hn / 2);
    } else {
        int r2 = row - B_ * Qn;
        // fk rows at/after valid_len are masked to p=0 in attn, skip them.
        if ((r2 & (Kn - 1)) >= valid_lens[r2 >> 10]) return;
        src = keys + (size_t)r2 * KSZ;
        Wp = (const u64*)Wk; biasp = (const u64*)bk;
        dst = (u64*)g_fk + (size_t)r2 * (Hn / 2);
    }

    const float4* s4 = (const float4*)src;
    u64 a0 = 0ull, a1 = 0ull, a2 = 0ull, a3 = 0ull;

    #pragma unroll 8
    for (int j4 = 0; j4 < QS / 4; j4++) {
        float4 x = __ldg(&s4[j4]);                       // broadcast within row-group
        const u64* wrow = Wp + (size_t)(4 * j4) * (Hn / 2) + hp;
        fma2(a0, pack2(x.x, x.x), __ldg(&wrow[0]));
        fma2(a1, pack2(x.y, x.y), __ldg(&wrow[Hn / 2]));
        fma2(a2, pack2(x.z, x.z), __ldg(&wrow[Hn]));
        fma2(a3, pack2(x.w, x.w), __ldg(&wrow[3 * Hn / 2]));
    }

    u64 r = add2(add2(a0, a1), add2(a2, a3));
    r = add2(r, __ldg(&biasp[hp]));
    dst[hp] = r;
}

// ---------------- kernel 2: fused additive attention ----------------
// grid = (B, Q/TQ), block = 256 (8 warps), 3 CTAs/SM (best-known config).
// Phase A: warp w = q-row w, lanes = k (4/lane), scalar tanh path, sacc split
// into even/odd-hb chains (16-deep FMA chains, 8-way ILP). No online softmax
// (scores bounded by ||w_v||_1 since |tanh|<=1 -> exp can't overflow in fp32).
// Phase B: warp w = (k-slice (w>>1)*32, v-half (w&1)*128); acc = 8q x 2 u64.
// fk_s AND pT2 double-buffered; ONE barrier per chunk; cp.async fk prefetch.

__global__ __launch_bounds__(256, 3)
void attn_kernel(const float* __restrict__ values, const int* __restrict__ valid_lens,
                 const float* __restrict__ wvec, float* __restrict__ out) {
    __shared__ float fk_s[2][TK * 36];                   // [k][h], stride 36 floats
    __shared__ __align__(16) u64 pT2[2][TK * 10];        // [k][q] dup pair {p,p}, stride 10 u64
    __shared__ float fq_s[TQ * 32];
    __shared__ float wv_s[32];
    __shared__ float l_s[TQ];

    const int tid  = threadIdx.x;
    const int w    = tid >> 5;
    const int lane = tid & 31;
    const int b    = blockIdx.x;
    const int q0   = blockIdx.y * TQ;
    const int valid = valid_lens[b];

    fq_s[w * 32 + lane] = g_fq[((size_t)(b * Qn + q0 + w)) * Hn + lane];
    if (tid < 32) wv_s[tid] = wvec[tid];

    float l_run = 0.0f;                   // per-lane partial row-sum for q=w
    u64 acc[TQ][2];                       // 8q x (4 floats of this warp's v-half)
    #pragma unroll
    for (int q = 0; q < TQ; q++) { acc[q][0] = 0ull; acc[q][1] = 0ull; }

    const float* vbatch = values + (size_t)b * Kn * VD;
    const int nchunks = (valid + TK - 1) / TK;

    // Preload chunk 0 into buffer 0 via cp.async
    {
        const float4* src = (const float4*)(g_fk + ((size_t)(b * Kn)) * Hn);
        #pragma unroll
        for (int r = 0; r < 4; r++) {
            int idx = tid + 256 * r;
            unsigned int dst = (unsigned int)__cvta_generic_to_shared(
                &((float4*)fk_s[0])[(idx >> 3) * 9 + (idx & 7)]);
            cp_async16(dst, &src[idx]);
        }
        cp_async_commit();
        cp_async_wait0();
    }
    __syncthreads();

    int buf = 0;
    for (int c = 0; c < nchunks; c++) {
        const int kb = c * TK;
        const bool full = (kb + TK <= valid);
        const bool has_next = (c + 1 < nchunks);

        // ---- Prefetch next fk chunk straight into the spare smem buffer ----
        if (has_next) {
            const float4* src = (const float4*)(g_fk + ((size_t)(b * Kn + kb + TK)) * Hn);
            #pragma unroll
            for (int r = 0; r < 4; r++) {
                int idx = tid + 256 * r;
                unsigned int dst = (unsigned int)__cvta_generic_to_shared(
                    &((float4*)fk_s[buf ^ 1])[(idx >> 3) * 9 + (idx & 7)]);
                cp_async16(dst, &src[idx]);
            }
            cp_async_commit();
        }

        // -------- Phase A: scores for q=w, k=lane+32i (split even/odd-hb chains) --------
        float sacc[4][2];
        #pragma unroll
        for (int i = 0; i < 4; i++) { sacc[i][0] = 0.f; sacc[i][1] = 0.f; }
        {
            const float4* fq4 = (const float4*)(fq_s + w * 32);
            const float4* wv4 = (const float4*)wv_s;
            const float4* fk4 = (const float4*)fk_s[buf];
            #pragma unroll
            for (int hb = 0; hb < 8; hb++) {
                float4 a = fq4[hb];
                float4 g = wv4[hb];
                const int s = hb & 1;
                #pragma unroll
                for (int i = 0; i < 4; i++) {
                    float4 f = fk4[(lane + 32 * i) * 9 + hb];
                    sacc[i][s] = fmaf(g.x, fast_tanh(a.x + f.x), sacc[i][s]);
                    sacc[i][s] = fmaf(g.y, fast_tanh(a.y + f.y), sacc[i][s]);
                    sacc[i][s] = fmaf(g.z, fast_tanh(a.z + f.z), sacc[i][s]);
                    sacc[i][s] = fmaf(g.w, fast_tanh(a.w + f.w), sacc[i][s]);
                }
            }
        }

        // -------- p = exp(score) (bounded, no max shift), mask, store dup-pair --------
        if (full) {
            #pragma unroll
            for (int i = 0; i < 4; i++) {
                float p = __expf(sacc[i][0] + sacc[i][1]);
                l_run += p;
                pT2[buf][(lane + 32 * i) * 10 + w] = pack2(p, p);
            }
        } else {
            #pragma unroll
            for (int i = 0; i < 4; i++) {
                float p = (kb + lane + 32 * i < valid) ? __expf(sacc[i][0] + sacc[i][1]) : 0.0f;
                l_run += p;
                pT2[buf][(lane + 32 * i) * 10 + w] = pack2(p, p);
            }
        }

        if (has_next) cp_async_wait0();
        __syncthreads();   // pT2[buf] visible; fk_s[buf^1] filled for next A

        // -------- Phase B: P@V. warp w = (k-slice (w>>1)*32, v-half (w&1)*128) --------
        {
            const int kloc0 = (w >> 1) * 32;
            const int voff  = (w & 1) * 128;
            const u64* pbase = pT2[buf] + kloc0 * 10;
            const float* vb = vbatch + (size_t)(kb + kloc0) * VD + voff;

            int kend;
            if (full) kend = 32;
            else { int rem = valid - kb - kloc0; kend = rem < 32 ? (rem < 0 ? 0 : rem) : 32; }

            #pragma unroll 4
            for (int kk = 0; kk < kend; kk++) {
                ulonglong2 v = __ldg((const ulonglong2*)(vb + (size_t)kk * VD) + lane);
                const ulonglong2* prow2 = (const ulonglong2*)(pbase + kk * 10);
                #pragma unroll
                for (int qp = 0; qp < 4; qp++) {
                    ulonglong2 pp = prow2[qp];       // broadcast LDS.128
                    fma2(acc[2 * qp][0],     v.x, pp.x);
                    fma2(acc[2 * qp][1],     v.y, pp.x);
                    fma2(acc[2 * qp + 1][0], v.x, pp.y);
                    fma2(acc[2 * qp + 1][1], v.y, pp.y);
                }
            }
        }
        buf ^= 1;
    }

    // -------- Epilogue: row-sums, then single-barrier cross-warp reduction --------
    float l = warp_sum(l_run);
    if (lane == 0) l_s[w] = l;

    // bufp layout: [q][w][128] floats = 32KB, lives in fk_s (36KB+)
    float* bufp = fk_s[0];
    #pragma unroll
    for (int q = 0; q < TQ; q++) {
        float f0, f1, f2, f3;
        unpack2(acc[q][0], f0, f1);
        unpack2(acc[q][1], f2, f3);
        float* d = bufp + (q * 8 + w) * 128 + lane * 4;
        d[0] = f0; d[1] = f1; d[2] = f2; d[3] = f3;
    }
    __syncthreads();

    // out element (q, v=tid): sum the 4 warps holding v-half (tid>>7)
    {
        const int vhalf = tid >> 7;
        const int idx   = tid & 127;
        const size_t obase = ((size_t)(b * Qn + q0)) * VD + tid;
        #pragma unroll
        for (int q = 0; q < TQ; q++) {
            const float* s = bufp + q * 1024 + vhalf * 128 + idx;
            float tot = s[0] + s[256] + s[512] + s[768];
            out[obase + (size_t)q * VD] = tot * (1.0f / l_s[q]);
        }
    }
}

// ---------------- launch ----------------

extern "C" void kernel_launch(void* const* d_in, const int* in_sizes, int n_in,
                              void* d_out, int out_size) {
    const float* keys       = (const float*)d_in[0];
    const float* queries    = (const float*)d_in[1];
    const float* values     = (const float*)d_in[2];
    const int*   valid_lens = (const int*)d_in[3];
    const float* W_q        = (const float*)d_in[4];
    const float* b_q        = (const float*)d_in[5];
    const float* W_k        = (const float*)d_in[6];
    const float* b_k        = (const float*)d_in[7];
    const float* w_v        = (const float*)d_in[8];
    // b_v (d_in[9]) is softmax-invariant and intentionally unused.
    float* out = (float*)d_out;

    int total_rows = B_ * (Qn + Kn);            // 8192
    proj_kernel<<<total_rows / 16, 256>>>(queries, keys, W_q, b_q, W_k, b_k, valid_lens);

    dim3 grid(B_, Qn / TQ);
    attn_kernel<<<grid, 256>>>(values, valid_lens, w_v, out);
}

// round 10
// speedup vs baseline: 1.2327x; 1.0005x over previous
#include <cuda_runtime.h>
#include <cstdint>

#define B_  4
#define Qn  1024
#define Kn  1024
#define QS  256
#define KSZ 256
#define Hn  32
#define VD  256
#define TQ  8
#define TK  128

// Device-global scratch (no runtime allocation allowed)
__device__ float g_fq[B_ * Qn * Hn];
__device__ float g_fk[B_ * Kn * Hn];

typedef unsigned long long u64;

// ---------------- helpers ----------------

__device__ __forceinline__ float fast_tanh(float x) {
    float y;
    asm("tanh.approx.f32 %0, %1;" : "=f"(y) : "f"(x));
    return y;
}

__device__ __forceinline__ float warp_sum(float v) {
    #pragma unroll
    for (int o = 16; o > 0; o >>= 1) v += __shfl_xor_sync(0xFFFFFFFFu, v, o);
    return v;
}

__device__ __forceinline__ u64 pack2(float lo, float hi) {
    u64 r;
    asm("mov.b64 %0, {%1, %2};" : "=l"(r) : "f"(lo), "f"(hi));
    return r;
}
__device__ __forceinline__ void unpack2(u64 a, float& lo, float& hi) {
    asm("mov.b64 {%0, %1}, %2;" : "=f"(lo), "=f"(hi) : "l"(a));
}
__device__ __forceinline__ u64 add2(u64 a, u64 b) {
    u64 r;
    asm("add.rn.f32x2 %0, %1, %2;" : "=l"(r) : "l"(a), "l"(b));
    return r;
}
__device__ __forceinline__ void fma2(u64& a, u64 v, u64 p) {
    asm("fma.rn.f32x2 %0, %1, %2, %0;" : "+l"(a) : "l"(v), "l"(p));
}

__device__ __forceinline__ void cp_async16(unsigned int dst_smem, const void* src) {
    asm volatile("cp.async.ca.shared.global [%0], [%1], 16;" :: "r"(dst_smem), "l"(src));
}
__device__ __forceinline__ void cp_async_commit() {
    asm volatile("cp.async.commit_group;");
}
__device__ __forceinline__ void cp_async_wait0() {
    asm volatile("cp.async.wait_group 0;");
}

// ---------------- kernel 1: projections fq = q@Wq+bq, fk = k@Wk+bk ----------------
// warp = 4 rows: rg = lane>>4 selects row pair, thread computes rows (base+rg)
// and (base+rg+2) so each W h-pair LDG.64 is shared by 2 rows. hp = lane&15.

__global__ __launch_bounds__(256)
void proj_kernel(const float* __restrict__ queries, const float* __restrict__ keys,
                 const float* __restrict__ Wq, const float* __restrict__ bq,
                 const float* __restrict__ Wk, const float* __restrict__ bk,
                 const int* __restrict__ valid_lens) {
    const int wid  = threadIdx.x >> 5;
    const int lane = threadIdx.x & 31;
    const int hp   = lane & 15;          // h-pair index: h = 2hp, 2hp+1
    const int rg   = lane >> 4;          // row-group
    const int base = (blockIdx.x * 8 + wid) * 4;
    const int r0   = base + rg;
    const int r1   = base + rg + 2;

    const float* srcbase; const u64* Wp; const u64* biasp; u64* dstbase;
    bool st0 = true, st1 = true;
    if (base < B_ * Qn) {
        srcbase = queries; Wp = (const u64*)Wq; biasp = (const u64*)bq;
        dstbase = (u64*)g_fq;
    } else {
        int r2b = base - B_ * Qn;
        int valid = valid_lens[r2b >> 10];
        // all 4 rows share b; if the first is past valid_len, all are -> skip.
        if ((r2b & (Kn - 1)) >= valid) return;
        st0 = ((r0 - B_ * Qn) & (Kn - 1)) < valid;
        st1 = ((r1 - B_ * Qn) & (Kn - 1)) < valid;
        srcbase = keys - (size_t)(B_ * Qn) * KSZ;    // so srcbase + row*KSZ works
        Wp = (const u64*)Wk; biasp = (const u64*)bk;
        dstbase = (u64*)g_fk - (size_t)(B_ * Qn) * (Hn / 2);
    }

    const float4* s0 = (const float4*)(srcbase + (size_t)r0 * QS);
    const float4* s1 = (const float4*)(srcbase + (size_t)r1 * QS);

    u64 a00 = 0ull, a01 = 0ull, a10 = 0ull, a11 = 0ull;
    #pragma unroll 8
    for (int j4 = 0; j4 < QS / 4; j4++) {
        float4 x0 = __ldg(&s0[j4]);
        float4 x1 = __ldg(&s1[j4]);
        const u64* wrow = Wp + (size_t)(4 * j4) * (Hn / 2) + hp;
        u64 w0 = __ldg(&wrow[0]);
        u64 w1 = __ldg(&wrow[Hn / 2]);
        u64 w2 = __ldg(&wrow[Hn]);
        u64 w3 = __ldg(&wrow[3 * Hn / 2]);
        fma2(a00, pack2(x0.x, x0.x), w0);
        fma2(a01, pack2(x0.y, x0.y), w1);
        fma2(a00, pack2(x0.z, x0.z), w2);
        fma2(a01, pack2(x0.w, x0.w), w3);
        fma2(a10, pack2(x1.x, x1.x), w0);
        fma2(a11, pack2(x1.y, x1.y), w1);
        fma2(a10, pack2(x1.z, x1.z), w2);
        fma2(a11, pack2(x1.w, x1.w), w3);
    }

    u64 bias = __ldg(&biasp[hp]);
    if (st0) dstbase[(size_t)r0 * (Hn / 2) + hp] = add2(add2(a00, a01), bias);
    if (st1) dstbase[(size_t)r1 * (Hn / 2) + hp] = add2(add2(a10, a11), bias);
}

// ---------------- attn phase helpers (generic / masked paths) ----------------

__device__ __forceinline__ void phaseA(const float* fkbuf, const float* fq_w,
                                       const float* wv, u64* pdst,
                                       int w, int lane, int kb, int valid,
                                       float& l_run) {
    float sacc[4] = {0.f, 0.f, 0.f, 0.f};
    const float4* fq4 = (const float4*)fq_w;
    const float4* wv4 = (const float4*)wv;
    const float4* fk4 = (const float4*)fkbuf;
    #pragma unroll
    for (int hb = 0; hb < 8; hb++) {
        float4 a = fq4[hb];
        float4 g = wv4[hb];
        #pragma unroll
        for (int i = 0; i < 4; i++) {
            float4 f = fk4[(lane + 32 * i) * 9 + hb];
            sacc[i] = fmaf(g.x, fast_tanh(a.x + f.x), sacc[i]);
            sacc[i] = fmaf(g.y, fast_tanh(a.y + f.y), sacc[i]);
            sacc[i] = fmaf(g.z, fast_tanh(a.z + f.z), sacc[i]);
            sacc[i] = fmaf(g.w, fast_tanh(a.w + f.w), sacc[i]);
        }
    }
    #pragma unroll
    for (int i = 0; i < 4; i++) {
        float p = (kb + lane + 32 * i < valid) ? __expf(sacc[i]) : 0.0f;
        l_run += p;
        pdst[(lane + 32 * i) * 10 + w] = pack2(p, p);
    }
}

__device__ __forceinline__ void phaseB(const u64* psrc, const float* vbatch,
                                       int kb, int valid, int w, int lane,
                                       u64 acc[TQ][2]) {
    const int kloc0 = (w >> 1) * 32;
    const int voff  = (w & 1) * 128;
    const u64* pbase = psrc + kloc0 * 10;
    const float* vb = vbatch + (size_t)(kb + kloc0) * VD + voff;
    int rem = valid - kb - kloc0;
    int kend = rem < 32 ? (rem < 0 ? 0 : rem) : 32;
    #pragma unroll 4
    for (int kk = 0; kk < kend; kk++) {
        ulonglong2 v = __ldg((const ulonglong2*)(vb + (size_t)kk * VD) + lane);
        const ulonglong2* prow2 = (const ulonglong2*)(pbase + kk * 10);
        #pragma unroll
        for (int qp = 0; qp < 4; qp++) {
            ulonglong2 pp = prow2[qp];
            fma2(acc[2 * qp][0],     v.x, pp.x);
            fma2(acc[2 * qp][1],     v.y, pp.x);
            fma2(acc[2 * qp + 1][0], v.x, pp.y);
            fma2(acc[2 * qp + 1][1], v.y, pp.y);
        }
    }
}

// ---------------- kernel 2: fused additive attention ----------------
// grid = (B, Q/TQ), block = 256 (8 warps), 3 CTAs/SM.
// Software-pipelined: region c executes A(c+1) [MUFU-heavy] AND B(c) [LSU/FMA-
// heavy] between the same barriers — no data dependency between them (A(c+1)
// writes pT2[(c+1)&1], B(c) reads pT2[c&1]) — with the common full/full case
// hand-interleaved (8 steps of {1 hb of A + 4 kk of B}) in ONE basic block so
// MUFU, FMA and LSU pipes are all fed simultaneously.
// No online softmax (|score| <= ||w_v||_1 since |tanh|<=1 -> exp safe in fp32).

__global__ __launch_bounds__(256, 3)
void attn_kernel(const float* __restrict__ values, const int* __restrict__ valid_lens,
                 const float* __restrict__ wvec, float* __restrict__ out) {
    __shared__ float fk_s[2][TK * 36];                   // [k][h], stride 36 floats
    __shared__ __align__(16) u64 pT2[2][TK * 10];        // [k][q] dup pair {p,p}, stride 10 u64
    __shared__ float fq_s[TQ * 32];
    __shared__ float wv_s[32];
    __shared__ float l_s[TQ];

    const int tid  = threadIdx.x;
    const int w    = tid >> 5;
    const int lane = tid & 31;
    const int b    = blockIdx.x;
    const int q0   = blockIdx.y * TQ;
    const int valid = valid_lens[b];

    fq_s[w * 32 + lane] = g_fq[((size_t)(b * Qn + q0 + w)) * Hn + lane];
    if (tid < 32) wv_s[tid] = wvec[tid];

    float l_run = 0.0f;
    u64 acc[TQ][2];
    #pragma unroll
    for (int q = 0; q < TQ; q++) { acc[q][0] = 0ull; acc[q][1] = 0ull; }

    const float* vbatch = values + (size_t)b * Kn * VD;
    const int nchunks = (valid + TK - 1) / TK;
    const int nfull   = valid / TK;

    // ---- Preload fk(0) into buffer 0 ----
    {
        const float4* src = (const float4*)(g_fk + ((size_t)(b * Kn)) * Hn);
        #pragma unroll
        for (int r = 0; r < 4; r++) {
            int idx = tid + 256 * r;
            unsigned int dst = (unsigned int)__cvta_generic_to_shared(
                &((float4*)fk_s[0])[(idx >> 3) * 9 + (idx & 7)]);
            cp_async16(dst, &src[idx]);
        }
        cp_async_commit();
        cp_async_wait0();
    }
    __syncthreads();

    // ---- Prologue: prefetch fk(1), compute A(0) ----
    if (nchunks > 1) {
        const float4* src = (const float4*)(g_fk + ((size_t)(b * Kn + TK)) * Hn);
        #pragma unroll
        for (int r = 0; r < 4; r++) {
            int idx = tid + 256 * r;
            unsigned int dst = (unsigned int)__cvta_generic_to_shared(
                &((float4*)fk_s[1])[(idx >> 3) * 9 + (idx & 7)]);
            cp_async16(dst, &src[idx]);
        }
        cp_async_commit();
    }
    phaseA(fk_s[0], fq_s + w * 32, wv_s, pT2[0], w, lane, 0, valid, l_run);
    if (nchunks > 1) cp_async_wait0();
    __syncthreads();

    // ---- Pipelined regions: region c = A(c+1) + B(c) ----
    for (int c = 0; c < nchunks; c++) {
        const int kb   = c * TK;
        const int bufB = c & 1;
        const int bufA = bufB ^ 1;

        if (c + 2 < nchunks) {     // prefetch fk(c+2) into fk_s[bufB] (fk(c) done)
            const float4* src = (const float4*)(g_fk + ((size_t)(b * Kn + kb + 2 * TK)) * Hn);
            #pragma unroll
            for (int r = 0; r < 4; r++) {
                int idx = tid + 256 * r;
                unsigned int dst = (unsigned int)__cvta_generic_to_shared(
                    &((float4*)fk_s[bufB])[(idx >> 3) * 9 + (idx & 7)]);
                cp_async16(dst, &src[idx]);
            }
            cp_async_commit();
        }

        if (c + 1 < nfull) {
            // ======== FAST PATH: A(c+1) full + B(c) full, hand-interleaved ========
            float sacc0 = 0.f, sacc1 = 0.f, sacc2 = 0.f, sacc3 = 0.f;
            const float4* fq4 = (const float4*)(fq_s + w * 32);
            const float4* wv4 = (const float4*)wv_s;
            const float4* fkA = (const float4*)fk_s[bufA];
            const int kloc0 = (w >> 1) * 32;
            const int voff  = (w & 1) * 128;
            const u64* pbase = pT2[bufB] + kloc0 * 10;
            const float* vb = vbatch + (size_t)(kb + kloc0) * VD + voff;

            #pragma unroll
            for (int s = 0; s < 8; s++) {
                // --- A slice: hb = s ---
                float4 a = fq4[s];
                float4 g = wv4[s];
                float4 f0 = fkA[(lane)       * 9 + s];
                float4 f1 = fkA[(lane + 32)  * 9 + s];
                float4 f2 = fkA[(lane + 64)  * 9 + s];
                float4 f3 = fkA[(lane + 96)  * 9 + s];
                sacc0 = fmaf(g.x, fast_tanh(a.x + f0.x), sacc0);
                sacc0 = fmaf(g.y, fast_tanh(a.y + f0.y), sacc0);
                sacc0 = fmaf(g.z, fast_tanh(a.z + f0.z), sacc0);
                sacc0 = fmaf(g.w, fast_tanh(a.w + f0.w), sacc0);
                sacc1 = fmaf(g.x, fast_tanh(a.x + f1.x), sacc1);
                sacc1 = fmaf(g.y, fast_tanh(a.y + f1.y), sacc1);
                sacc1 = fmaf(g.z, fast_tanh(a.z + f1.z), sacc1);
                sacc1 = fmaf(g.w, fast_tanh(a.w + f1.w), sacc1);
                sacc2 = fmaf(g.x, fast_tanh(a.x + f2.x), sacc2);
                sacc2 = fmaf(g.y, fast_tanh(a.y + f2.y), sacc2);
                sacc2 = fmaf(g.z, fast_tanh(a.z + f2.z), sacc2);
                sacc2 = fmaf(g.w, fast_tanh(a.w + f2.w), sacc2);
                sacc3 = fmaf(g.x, fast_tanh(a.x + f3.x), sacc3);
                sacc3 = fmaf(g.y, fast_tanh(a.y + f3.y), sacc3);
                sacc3 = fmaf(g.z, fast_tanh(a.z + f3.z), sacc3);
                sacc3 = fmaf(g.w, fast_tanh(a.w + f3.w), sacc3);
                // --- B slice: kk = 4s .. 4s+3 ---
                #pragma unroll
                for (int t = 0; t < 4; t++) {
                    int kk = 4 * s + t;
                    ulonglong2 v = __ldg((const ulonglong2*)(vb + (size_t)kk * VD) + lane);
                    const ulonglong2* prow2 = (const ulonglong2*)(pbase + kk * 10);
                    #pragma unroll
                    for (int qp = 0; qp < 4; qp++) {
                        ulonglong2 pp = prow2[qp];
                        fma2(acc[2 * qp][0],     v.x, pp.x);
                        fma2(acc[2 * qp][1],     v.y, pp.x);
                        fma2(acc[2 * qp + 1][0], v.x, pp.y);
                        fma2(acc[2 * qp + 1][1], v.y, pp.y);
                    }
                }
            }
            // A epilogue (full chunk: no mask)
            float p0 = __expf(sacc0), p1 = __expf(sacc1);
            float p2 = __expf(sacc2), p3 = __expf(sacc3);
            l_run += (p0 + p1) + (p2 + p3);
            pT2[bufA][(lane)       * 10 + w] = pack2(p0, p0);
            pT2[bufA][(lane + 32)  * 10 + w] = pack2(p1, p1);
            pT2[bufA][(lane + 64)  * 10 + w] = pack2(p2, p2);
            pT2[bufA][(lane + 96)  * 10 + w] = pack2(p3, p3);
        } else {
            // ======== GENERIC PATH (tail chunks) ========
            if (c + 1 < nchunks)
                phaseA(fk_s[bufA], fq_s + w * 32, wv_s, pT2[bufA],
                       w, lane, kb + TK, valid, l_run);
            phaseB(pT2[bufB], vbatch, kb, valid, w, lane, acc);
        }

        if (c + 2 < nchunks) cp_async_wait0();
        __syncthreads();
    }

    // -------- Epilogue: row-sums, then single-barrier cross-warp reduction --------
    float l = warp_sum(l_run);
    if (lane == 0) l_s[w] = l;

    float* bufp = fk_s[0];   // 32KB scratch inside fk_s
    #pragma unroll
    for (int q = 0; q < TQ; q++) {
        float f0, f1, f2, f3;
        unpack2(acc[q][0], f0, f1);
        unpack2(acc[q][1], f2, f3);
        float* d = bufp + (q * 8 + w) * 128 + lane * 4;
        d[0] = f0; d[1] = f1; d[2] = f2; d[3] = f3;
    }
    __syncthreads();

    {
        const int vhalf = tid >> 7;
        const int idx   = tid & 127;
        const size_t obase = ((size_t)(b * Qn + q0)) * VD + tid;
        #pragma unroll
        for (int q = 0; q < TQ; q++) {
            const float* s = bufp + q * 1024 + vhalf * 128 + idx;
            float tot = s[0] + s[256] + s[512] + s[768];
            out[obase + (size_t)q * VD] = tot * (1.0f / l_s[q]);
        }
    }
}

// ---------------- launch ----------------

extern "C" void kernel_launch(void* const* d_in, const int* in_sizes, int n_in,
                              void* d_out, int out_size) {
    const float* keys       = (const float*)d_in[0];
    const float* queries    = (const float*)d_in[1];
    const float* values     = (const float*)d_in[2];
    const int*   valid_lens = (const int*)d_in[3];
    const float* W_q        = (const float*)d_in[4];
    const float* b_q        = (const float*)d_in[5];
    const float* W_k        = (const float*)d_in[6];
    const float* b_k        = (const float*)d_in[7];
    const float* w_v        = (const float*)d_in[8];
    // b_v (d_in[9]) is softmax-invariant and intentionally unused.
    float* out = (float*)d_out;

    int total_rows = B_ * (Qn + Kn);            // 8192
    proj_kernel<<<total_rows / 32, 256>>>(queries, keys, W_q, b_q, W_k, b_k, valid_lens);

    dim3 grid(B_, Qn / TQ);
    attn_kernel<<<grid, 256>>>(values, valid_lens, w_v, out);
}